// round 7
// baseline (speedup 1.0000x reference)
#include <cuda_runtime.h>
#include <cfloat>
#include <cstdint>
#include <math.h>

// Problem constants
#define NROWS   262144          // 8*32*32*32
#define DIM     256
#define KCODES  1024
#define NQ      67108864        // NROWS*DIM

// ---------------- scratch (no allocations allowed) ----------------
__device__ float  g_ee[KCODES];   // sum(e_k^2), sequential ascending fp32 chain
__device__ float  g_xx[NROWS];    // sum(x_i^2), sequential ascending fp32 chain
__device__ int    g_counts[KCODES];
__device__ double g_losssum;

// ---------------- kernel 1: codebook norms + zero scratch ----------------
// Sequential ascending chain: s = fl(s + fl(v*v)), d = 0..255  (XLA:CPU order)
__global__ void vq_prep(const float* __restrict__ cb) {
    int k = blockIdx.x * blockDim.x + threadIdx.x;
    if (k < KCODES) {
        const float4* p = (const float4*)(cb + (long long)k * DIM);
        float s = 0.f;
        #pragma unroll 8
        for (int i = 0; i < 64; ++i) {
            float4 v = __ldg(&p[i]);
            s = __fadd_rn(s, __fmul_rn(v.x, v.x));
            s = __fadd_rn(s, __fmul_rn(v.y, v.y));
            s = __fadd_rn(s, __fmul_rn(v.z, v.z));
            s = __fadd_rn(s, __fmul_rn(v.w, v.w));
        }
        g_ee[k] = s;
        g_counts[k] = 0;
    }
    if (blockIdx.x == 0 && threadIdx.x == 0) g_losssum = 0.0;
}

// ---------------- kernel 1b: per-row ||x||^2, sequential ascending chain ----------------
__global__ void vq_xx(const float* __restrict__ x) {
    long long r = (long long)blockIdx.x * blockDim.x + threadIdx.x;
    if (r >= NROWS) return;
    const float4* p = (const float4*)(x + r * DIM);
    float s = 0.f;
    #pragma unroll 8
    for (int i = 0; i < 64; ++i) {
        float4 v = __ldg(&p[i]);
        s = __fadd_rn(s, __fmul_rn(v.x, v.x));
        s = __fadd_rn(s, __fmul_rn(v.y, v.y));
        s = __fadd_rn(s, __fmul_rn(v.z, v.z));
        s = __fadd_rn(s, __fmul_rn(v.w, v.w));
    }
    g_xx[r] = s;
}

// ---------------- kernel 2: argmin-GEMM + fused epilogue ----------------
// Block: 128 rows vs all 1024 codes in 8 tiles of 128.
// Plain fp32 inputs; ascending-k single-accumulator FMA chain per output
// (Eigen gebp / XLA:CPU contraction order).
__global__ __launch_bounds__(256, 2)
void vq_main(const float* __restrict__ x,
             const float* __restrict__ cb,
             float* __restrict__ out) {
    __shared__ float As[8][132];
    __shared__ float Bs[8][132];
    __shared__ float red_v[128][16];
    __shared__ int   red_i[128][16];
    __shared__ float bestv[128];
    __shared__ int   besti[128];
    __shared__ float warp_ls[8];

    const int tid = threadIdx.x;
    const int ty  = tid >> 4;
    const int tx  = tid & 15;
    const long long row0 = (long long)blockIdx.x * 128;

    if (tid < 128) { bestv[tid] = FLT_MAX; besti[tid] = 0; }

    const int lrow = tid >> 1;
    const int ld4  = (tid & 1) * 4;

    float xxv[8];
    #pragma unroll
    for (int i = 0; i < 8; ++i) xxv[i] = __ldg(&g_xx[row0 + ty * 8 + i]);

    for (int ct = 0; ct < 8; ++ct) {
        const int code0 = ct * 128;

        float acc[8][8];
        #pragma unroll
        for (int i = 0; i < 8; ++i)
            #pragma unroll
            for (int j = 0; j < 8; ++j) acc[i][j] = 0.f;

        for (int s = 0; s < 32; ++s) {
            const int d0 = s * 8;
            float4 av = *(const float4*)&x [(row0 + lrow) * DIM + d0 + ld4];
            float4 bv = *(const float4*)&cb[(long long)(code0 + lrow) * DIM + d0 + ld4];

            __syncthreads();
            As[ld4 + 0][lrow] = av.x; As[ld4 + 1][lrow] = av.y;
            As[ld4 + 2][lrow] = av.z; As[ld4 + 3][lrow] = av.w;
            Bs[ld4 + 0][lrow] = bv.x; Bs[ld4 + 1][lrow] = bv.y;
            Bs[ld4 + 2][lrow] = bv.z; Bs[ld4 + 3][lrow] = bv.w;
            __syncthreads();

            #pragma unroll
            for (int d = 0; d < 8; ++d) {     // k = 8*s + d, strictly ascending
                float4 a0 = *(const float4*)&As[d][ty * 8];
                float4 a1 = *(const float4*)&As[d][ty * 8 + 4];
                float4 b0 = *(const float4*)&Bs[d][tx * 8];
                float4 b1 = *(const float4*)&Bs[d][tx * 8 + 4];
                float a[8] = {a0.x, a0.y, a0.z, a0.w, a1.x, a1.y, a1.z, a1.w};
                float b[8] = {b0.x, b0.y, b0.z, b0.w, b1.x, b1.y, b1.z, b1.w};
                #pragma unroll
                for (int i = 0; i < 8; ++i)
                    #pragma unroll
                    for (int j = 0; j < 8; ++j)
                        acc[i][j] = fmaf(a[i], b[j], acc[i][j]);
            }
        }

        // reference-rounded distances: fl(fl(xx+ee) - fl(2*mm)); argmin lowest-index
        float cv[8];
        #pragma unroll
        for (int j = 0; j < 8; ++j) cv[j] = __ldg(&g_ee[code0 + tx * 8 + j]);

        #pragma unroll
        for (int i = 0; i < 8; ++i) {
            float bv_ = FLT_MAX;
            int   bi_ = code0 + tx * 8;
            #pragma unroll
            for (int j = 0; j < 8; ++j) {     // ascending index + strict < => lowest idx on tie
                float t = __fadd_rn(xxv[i], cv[j]);
                float v = __fadd_rn(t, __fmul_rn(-2.0f, acc[i][j]));
                if (v < bv_) { bv_ = v; bi_ = code0 + tx * 8 + j; }
            }
            red_v[ty * 8 + i][tx] = bv_;
            red_i[ty * 8 + i][tx] = bi_;
        }
        __syncthreads();
        if (tid < 128) {
            float bv_ = bestv[tid]; int bi_ = besti[tid];
            #pragma unroll
            for (int t = 0; t < 16; ++t) {    // tx ascending == index ascending
                float v = red_v[tid][t];
                if (v < bv_) { bv_ = v; bi_ = red_i[tid][t]; }
            }
            bestv[tid] = bv_; besti[tid] = bi_;
        }
        __syncthreads();
    }

    // ---- fused output epilogue: gather, straight-through, loss, histogram ----
    const int wid = tid >> 5, lane = tid & 31;
    float ls = 0.f;
    for (int rr = 0; rr < 16; ++rr) {
        const int row = wid + rr * 8;
        const int idx = besti[row];
        const float* qrow = cb + (long long)idx * DIM;
        const float* xrow = x  + (row0 + row) * DIM;
        float*       orow = out + (row0 + row) * DIM;
        if (lane == 0) atomicAdd(&g_counts[idx], 1);
        #pragma unroll
        for (int d = lane; d < DIM; d += 32) {
            float q  = __ldg(&qrow[d]);
            float xv = xrow[d];
            float df = __fadd_rn(q, -xv);       // fl(q - x)
            orow[d]  = __fadd_rn(xv, df);       // fl(x + fl(q - x)) — matches jax ST
            ls = fmaf(df, df, ls);
        }
    }
    #pragma unroll
    for (int o = 16; o > 0; o >>= 1) ls += __shfl_xor_sync(0xffffffffu, ls, o);
    if (lane == 0) warp_ls[wid] = ls;
    __syncthreads();
    if (tid == 0) {
        float s = 0.f;
        #pragma unroll
        for (int w = 0; w < 8; ++w) s += warp_ls[w];
        atomicAdd(&g_losssum, (double)s);
    }
}

// ---------------- kernel 3: loss + perplexity ----------------
__global__ void vq_finalize(float* __restrict__ out) {
    __shared__ float sh[1024];
    const int t = threadIdx.x;
    float p = (float)g_counts[t] * (1.0f / (float)NROWS);
    sh[t] = p * logf(p + 1e-10f);
    __syncthreads();
    for (int o = 512; o > 0; o >>= 1) {
        if (t < o) sh[t] += sh[t + o];
        __syncthreads();
    }
    if (t == 0) {
        double mean = g_losssum / (double)NQ;
        float  m    = (float)mean;
        out[NQ]     = __fadd_rn(m, __fmul_rn(0.25f, m));  // q_loss + 0.25*e_loss
        out[NQ + 1] = expf(-sh[0]);
    }
}

// ---------------- launch ----------------
extern "C" void kernel_launch(void* const* d_in, const int* in_sizes, int n_in,
                              void* d_out, int out_size) {
    const float* x  = (const float*)d_in[0];
    const float* cb = (const float*)d_in[1];
    float* out = (float*)d_out;

    vq_prep<<<(KCODES + 255) / 256, 256>>>(cb);
    vq_xx<<<(NROWS + 255) / 256, 256>>>(x);
    vq_main<<<NROWS / 128, 256>>>(x, cb, out);
    vq_finalize<<<1, 1024>>>(out);
}

// round 8
// speedup vs baseline: 1.0006x; 1.0006x over previous
#include <cuda_runtime.h>
#include <cfloat>
#include <cstdint>
#include <math.h>

// Problem constants
#define NROWS   262144          // 8*32*32*32
#define DIM     256
#define KCODES  1024
#define NQ      67108864        // NROWS*DIM

// ---------------- scratch (no allocations allowed) ----------------
__device__ float  g_ee[KCODES];   // sum(e_k^2), sequential ascending fp32 chain
__device__ float  g_xx[NROWS];    // sum(x_i^2), sequential ascending fp32 chain
__device__ int    g_counts[KCODES];
__device__ double g_losssum;

// ---------------- kernel 1: codebook norms + zero scratch ----------------
// Sequential ascending chain: s = fl(s + fl(v*v)), d = 0..255  (XLA:CPU order)
__global__ void vq_prep(const float* __restrict__ cb) {
    int k = blockIdx.x * blockDim.x + threadIdx.x;
    if (k < KCODES) {
        const float4* p = (const float4*)(cb + (long long)k * DIM);
        float s = 0.f;
        #pragma unroll 8
        for (int i = 0; i < 64; ++i) {
            float4 v = __ldg(&p[i]);
            s = __fadd_rn(s, __fmul_rn(v.x, v.x));
            s = __fadd_rn(s, __fmul_rn(v.y, v.y));
            s = __fadd_rn(s, __fmul_rn(v.z, v.z));
            s = __fadd_rn(s, __fmul_rn(v.w, v.w));
        }
        g_ee[k] = s;
        g_counts[k] = 0;
    }
    if (blockIdx.x == 0 && threadIdx.x == 0) g_losssum = 0.0;
}

// ---------------- kernel 1b: per-row ||x||^2, sequential ascending chain ----------------
__global__ void vq_xx(const float* __restrict__ x) {
    long long r = (long long)blockIdx.x * blockDim.x + threadIdx.x;
    if (r >= NROWS) return;
    const float4* p = (const float4*)(x + r * DIM);
    float s = 0.f;
    #pragma unroll 8
    for (int i = 0; i < 64; ++i) {
        float4 v = __ldg(&p[i]);
        s = __fadd_rn(s, __fmul_rn(v.x, v.x));
        s = __fadd_rn(s, __fmul_rn(v.y, v.y));
        s = __fadd_rn(s, __fmul_rn(v.z, v.z));
        s = __fadd_rn(s, __fmul_rn(v.w, v.w));
    }
    g_xx[r] = s;
}

// ---------------- kernel 2: argmin-GEMM + fused epilogue ----------------
// Block: 128 rows vs all 1024 codes in 8 tiles of 128.
// Plain fp32 inputs; ascending-k single-accumulator FMA chain per output
// (Eigen gebp / XLA:CPU contraction order).
__global__ __launch_bounds__(256, 2)
void vq_main(const float* __restrict__ x,
             const float* __restrict__ cb,
             float* __restrict__ out) {
    __shared__ float As[8][132];
    __shared__ float Bs[8][132];
    __shared__ float red_v[128][16];
    __shared__ int   red_i[128][16];
    __shared__ float bestv[128];
    __shared__ int   besti[128];
    __shared__ float warp_ls[8];

    const int tid = threadIdx.x;
    const int ty  = tid >> 4;
    const int tx  = tid & 15;
    const long long row0 = (long long)blockIdx.x * 128;

    if (tid < 128) { bestv[tid] = FLT_MAX; besti[tid] = 0; }

    const int lrow = tid >> 1;
    const int ld4  = (tid & 1) * 4;

    float xxv[8];
    #pragma unroll
    for (int i = 0; i < 8; ++i) xxv[i] = __ldg(&g_xx[row0 + ty * 8 + i]);

    for (int ct = 0; ct < 8; ++ct) {
        const int code0 = ct * 128;

        float acc[8][8];
        #pragma unroll
        for (int i = 0; i < 8; ++i)
            #pragma unroll
            for (int j = 0; j < 8; ++j) acc[i][j] = 0.f;

        for (int s = 0; s < 32; ++s) {
            const int d0 = s * 8;
            float4 av = *(const float4*)&x [(row0 + lrow) * DIM + d0 + ld4];
            float4 bv = *(const float4*)&cb[(long long)(code0 + lrow) * DIM + d0 + ld4];

            __syncthreads();
            As[ld4 + 0][lrow] = av.x; As[ld4 + 1][lrow] = av.y;
            As[ld4 + 2][lrow] = av.z; As[ld4 + 3][lrow] = av.w;
            Bs[ld4 + 0][lrow] = bv.x; Bs[ld4 + 1][lrow] = bv.y;
            Bs[ld4 + 2][lrow] = bv.z; Bs[ld4 + 3][lrow] = bv.w;
            __syncthreads();

            #pragma unroll
            for (int d = 0; d < 8; ++d) {     // k = 8*s + d, strictly ascending
                float4 a0 = *(const float4*)&As[d][ty * 8];
                float4 a1 = *(const float4*)&As[d][ty * 8 + 4];
                float4 b0 = *(const float4*)&Bs[d][tx * 8];
                float4 b1 = *(const float4*)&Bs[d][tx * 8 + 4];
                float a[8] = {a0.x, a0.y, a0.z, a0.w, a1.x, a1.y, a1.z, a1.w};
                float b[8] = {b0.x, b0.y, b0.z, b0.w, b1.x, b1.y, b1.z, b1.w};
                #pragma unroll
                for (int i = 0; i < 8; ++i)
                    #pragma unroll
                    for (int j = 0; j < 8; ++j)
                        acc[i][j] = fmaf(a[i], b[j], acc[i][j]);
            }
        }

        // reference-rounded distances: fl(fl(xx+ee) - fl(2*mm)); argmin lowest-index
        float cv[8];
        #pragma unroll
        for (int j = 0; j < 8; ++j) cv[j] = __ldg(&g_ee[code0 + tx * 8 + j]);

        #pragma unroll
        for (int i = 0; i < 8; ++i) {
            float bv_ = FLT_MAX;
            int   bi_ = code0 + tx * 8;
            #pragma unroll
            for (int j = 0; j < 8; ++j) {     // ascending index + strict < => lowest idx on tie
                float t = __fadd_rn(xxv[i], cv[j]);
                float v = __fadd_rn(t, __fmul_rn(-2.0f, acc[i][j]));
                if (v < bv_) { bv_ = v; bi_ = code0 + tx * 8 + j; }
            }
            red_v[ty * 8 + i][tx] = bv_;
            red_i[ty * 8 + i][tx] = bi_;
        }
        __syncthreads();
        if (tid < 128) {
            float bv_ = bestv[tid]; int bi_ = besti[tid];
            #pragma unroll
            for (int t = 0; t < 16; ++t) {    // tx ascending == index ascending
                float v = red_v[tid][t];
                if (v < bv_) { bv_ = v; bi_ = red_i[tid][t]; }
            }
            bestv[tid] = bv_; besti[tid] = bi_;
        }
        __syncthreads();
    }

    // ---- fused output epilogue: gather, straight-through, loss, histogram ----
    const int wid = tid >> 5, lane = tid & 31;
    float ls = 0.f;
    for (int rr = 0; rr < 16; ++rr) {
        const int row = wid + rr * 8;
        const int idx = besti[row];
        const float* qrow = cb + (long long)idx * DIM;
        const float* xrow = x  + (row0 + row) * DIM;
        float*       orow = out + (row0 + row) * DIM;
        if (lane == 0) atomicAdd(&g_counts[idx], 1);
        #pragma unroll
        for (int d = lane; d < DIM; d += 32) {
            float q  = __ldg(&qrow[d]);
            float xv = xrow[d];
            float df = __fadd_rn(q, -xv);       // fl(q - x)
            orow[d]  = __fadd_rn(xv, df);       // fl(x + fl(q - x)) — matches jax ST
            ls = fmaf(df, df, ls);
        }
    }
    #pragma unroll
    for (int o = 16; o > 0; o >>= 1) ls += __shfl_xor_sync(0xffffffffu, ls, o);
    if (lane == 0) warp_ls[wid] = ls;
    __syncthreads();
    if (tid == 0) {
        float s = 0.f;
        #pragma unroll
        for (int w = 0; w < 8; ++w) s += warp_ls[w];
        atomicAdd(&g_losssum, (double)s);
    }
}

// ---------------- kernel 3: loss + perplexity ----------------
__global__ void vq_finalize(float* __restrict__ out) {
    __shared__ float sh[1024];
    const int t = threadIdx.x;
    float p = (float)g_counts[t] * (1.0f / (float)NROWS);
    sh[t] = p * logf(p + 1e-10f);
    __syncthreads();
    for (int o = 512; o > 0; o >>= 1) {
        if (t < o) sh[t] += sh[t + o];
        __syncthreads();
    }
    if (t == 0) {
        double mean = g_losssum / (double)NQ;
        float  m    = (float)mean;
        out[NQ]     = __fadd_rn(m, __fmul_rn(0.25f, m));  // q_loss + 0.25*e_loss
        out[NQ + 1] = expf(-sh[0]);
    }
}

// ---------------- launch ----------------
extern "C" void kernel_launch(void* const* d_in, const int* in_sizes, int n_in,
                              void* d_out, int out_size) {
    const float* x  = (const float*)d_in[0];
    const float* cb = (const float*)d_in[1];
    float* out = (float*)d_out;

    vq_prep<<<(KCODES + 255) / 256, 256>>>(cb);
    vq_xx<<<(NROWS + 255) / 256, 256>>>(x);
    vq_main<<<NROWS / 128, 256>>>(x, cb, out);
    vq_finalize<<<1, 1024>>>(out);
}

// round 10
// speedup vs baseline: 1.5048x; 1.5038x over previous
#include <cuda_runtime.h>
#include <cuda_bf16.h>
#include <cfloat>
#include <cstdint>
#include <math.h>

#define NROWS   262144
#define DIM     256
#define KCODES  1024
#define NQ      67108864
#define MARGIN  8e-4f

// ---------------- scratch (no allocations) ----------------
__device__ float  g_ee[KCODES];
__device__ int    g_counts[KCODES];
__device__ double g_losssum;
__device__ __align__(1024) unsigned char g_cb_sw[8 * 65536]; // bf16 codebook, 8 N-tiles, swizzled rows
__device__ unsigned g_cand[NROWS * 9];                        // [count][8 x packed u16 idx]

// ---------------- PTX helpers (baseline sm_80/90 features only) ----------------
__device__ __forceinline__ unsigned smem_u32(const void* p) {
    unsigned a;
    asm("{ .reg .u64 t; cvta.to.shared.u64 t, %1; cvt.u32.u64 %0, t; }" : "=r"(a) : "l"(p));
    return a;
}
#define CP16(dst, src) asm volatile("cp.async.cg.shared.global [%0], [%1], 16;" :: "r"(dst), "l"(src) : "memory")
#define CP_COMMIT()    asm volatile("cp.async.commit_group;" ::: "memory")
#define CP_WAIT0()     asm volatile("cp.async.wait_group 0;" ::: "memory")
#define LDSM4(r, a) \
    asm volatile("ldmatrix.sync.aligned.m8n8.x4.shared.b16 {%0,%1,%2,%3}, [%4];" \
        : "=r"((r)[0]), "=r"((r)[1]), "=r"((r)[2]), "=r"((r)[3]) : "r"(a))

__device__ __forceinline__ void mma16816(float* d, const unsigned* a, unsigned b0, unsigned b1) {
    asm volatile("mma.sync.aligned.m16n8k16.row.col.f32.bf16.bf16.f32 "
        "{%0,%1,%2,%3}, {%4,%5,%6,%7}, {%8,%9}, {%0,%1,%2,%3};"
        : "+f"(d[0]), "+f"(d[1]), "+f"(d[2]), "+f"(d[3])
        : "r"(a[0]), "r"(a[1]), "r"(a[2]), "r"(a[3]), "r"(b0), "r"(b1));
}

// Row layout: 512B per row (256 bf16), 32 chunks of 16B, chunk XOR-swizzled by row&7
// -> conflict-free ldmatrix (each 8-lane group's rows span the full 8-phase orbit).
__device__ __forceinline__ unsigned sw_off(int row, int k8) {   // k8 = element idx, multiple of 8
    return (unsigned)row * 512u + (unsigned)(((k8 >> 3) ^ (row & 7)) << 4);
}

// ---------------- kernel 1: exact ee chains + swizzled bf16 codebook + zero scratch ----------------
__global__ void vq_prep(const float* __restrict__ cb) {
    int gt = blockIdx.x * blockDim.x + threadIdx.x;
    if (gt < KCODES) {
        const float4* p = (const float4*)(cb + (long long)gt * DIM);
        float s = 0.f;
        #pragma unroll 8
        for (int i = 0; i < 64; ++i) {
            float4 v = __ldg(&p[i]);
            s = __fadd_rn(s, __fmul_rn(v.x, v.x));
            s = __fadd_rn(s, __fmul_rn(v.y, v.y));
            s = __fadd_rn(s, __fmul_rn(v.z, v.z));
            s = __fadd_rn(s, __fmul_rn(v.w, v.w));
        }
        g_ee[gt] = s;
        g_counts[gt] = 0;
    }
    if (gt == 0) g_losssum = 0.0;
    // pre-swizzled bf16 codebook: tile t holds codes [128t,128t+128) as rows
    for (int i = gt * 8; i < KCODES * DIM; i += gridDim.x * blockDim.x * 8) {
        int code = i >> 8, k8 = i & 255;
        float4 f0 = __ldg((const float4*)(cb + i));
        float4 f1 = __ldg((const float4*)(cb + i) + 1);
        __nv_bfloat162 h0 = __floats2bfloat162_rn(f0.x, f0.y);
        __nv_bfloat162 h1 = __floats2bfloat162_rn(f0.z, f0.w);
        __nv_bfloat162 h2 = __floats2bfloat162_rn(f1.x, f1.y);
        __nv_bfloat162 h3 = __floats2bfloat162_rn(f1.z, f1.w);
        uint4 w = make_uint4(*(unsigned*)&h0, *(unsigned*)&h1, *(unsigned*)&h2, *(unsigned*)&h3);
        *(uint4*)(g_cb_sw + (code >> 7) * 65536 + sw_off(code & 127, k8)) = w;
    }
}

// ---------------- kernel 2: HMMA bf16 screening GEMM + candidate collection ----------------
#define EE_OFF    0
#define A_OFF     4096
#define B_OFF     69632
#define DIST_OFF  135168
#define DSTRIDE   136
#define SMEM_MMA  204800

__global__ __launch_bounds__(256, 1)
void vq_mma(const float* __restrict__ x) {
    extern __shared__ char smem[];
    const unsigned sb = smem_u32(smem);
    float* ee_s   = (float*)(smem + EE_OFF);
    float* dist_s = (float*)(smem + DIST_OFF);
    const int tid = threadIdx.x, wid = tid >> 5, lane = tid & 31;
    const long long row0 = (long long)blockIdx.x * 128;

    #pragma unroll
    for (int i = 0; i < 4; ++i) ee_s[tid + i * 256] = g_ee[tid + i * 256];

    // kick off B tile 0 (pure 16B copy: already swizzled in gmem)
    #pragma unroll
    for (int j = 0; j < 16; ++j) {
        unsigned off = (unsigned)(tid + j * 256) * 16u;
        CP16(sb + B_OFF + off, (const char*)g_cb_sw + off);
    }
    CP_COMMIT();

    // build A: 128 rows x 256 k -> bf16 swizzled (coalesced ldg, conflict-free sts)
    #pragma unroll
    for (int i = 0; i < 16; ++i) {
        int c = tid + i * 256;                  // 0..4095
        int row = c >> 5, kc = (c & 31) * 8;
        const float4* gp = (const float4*)(x + (row0 + row) * DIM + kc);
        float4 f0 = __ldg(gp), f1 = __ldg(gp + 1);
        __nv_bfloat162 h0 = __floats2bfloat162_rn(f0.x, f0.y);
        __nv_bfloat162 h1 = __floats2bfloat162_rn(f0.z, f0.w);
        __nv_bfloat162 h2 = __floats2bfloat162_rn(f1.x, f1.y);
        __nv_bfloat162 h3 = __floats2bfloat162_rn(f1.z, f1.w);
        uint4 w = make_uint4(*(unsigned*)&h0, *(unsigned*)&h1, *(unsigned*)&h2, *(unsigned*)&h3);
        *(uint4*)(smem + A_OFF + sw_off(row, kc)) = w;
    }
    CP_WAIT0();
    __syncthreads();

    // warp tiling: 4 (rows) x 2 (cols); warp = 32 rows x 64 cols
    const int mrow0 = (wid >> 1) * 32;
    const int ncol0 = (wid & 1) * 64;
    const int arow  = lane & 15;            // ldmatrix A lane row within m16
    const int akc   = lane >> 4;            // A k-chunk (0/1)
    const int bn    = ((lane >> 4) << 3) + (lane & 7);   // ldmatrix B lane row within n16
    const int bkc   = (lane >> 3) & 1;      // B k-chunk (0/1)

    // per-row candidate state (threads 0..127 own row = tid)
    float v1 = FLT_MAX; int cnt = 0; bool ovf = false;
    float cval[16]; unsigned short cidx[16];

    for (int t = 0; t < 8; ++t) {
        float acc[2][8][4];
        #pragma unroll
        for (int mt = 0; mt < 2; ++mt)
            #pragma unroll
            for (int j = 0; j < 8; ++j)
                #pragma unroll
                for (int q = 0; q < 4; ++q) acc[mt][j][q] = 0.f;

        #pragma unroll
        for (int ks = 0; ks < 16; ++ks) {
            unsigned a[2][4], b[4][4];
            #pragma unroll
            for (int mt = 0; mt < 2; ++mt) {
                int r = mrow0 + mt * 16 + arow;
                LDSM4(a[mt], sb + A_OFF + (unsigned)r * 512u + (unsigned)(((ks * 2 + akc) ^ (r & 7)) << 4));
            }
            #pragma unroll
            for (int nt = 0; nt < 4; ++nt) {
                int n = ncol0 + nt * 16 + bn;
                LDSM4(b[nt], sb + B_OFF + (unsigned)n * 512u + (unsigned)(((ks * 2 + bkc) ^ (n & 7)) << 4));
            }
            #pragma unroll
            for (int mt = 0; mt < 2; ++mt)
                #pragma unroll
                for (int j = 0; j < 8; ++j)
                    mma16816(acc[mt][j], a[mt], b[j >> 1][(j & 1) * 2], b[j >> 1][(j & 1) * 2 + 1]);
        }
        __syncthreads();                    // B(t) fully consumed

        if (t < 7) {                        // prefetch B(t+1) over dist+scan phase
            #pragma unroll
            for (int j = 0; j < 16; ++j) {
                unsigned off = (unsigned)(tid + j * 256) * 16u;
                CP16(sb + B_OFF + off, (const char*)g_cb_sw + (t + 1) * 65536 + off);
            }
            CP_COMMIT();
        }

        // screened distances -> dist_s[col][row] (stride 136: conflict-free scan)
        const int r0 = mrow0 + (lane >> 2);
        #pragma unroll
        for (int mt = 0; mt < 2; ++mt)
            #pragma unroll
            for (int j = 0; j < 8; ++j) {
                int cl = ncol0 + j * 8 + (lane & 3) * 2;
                float e0 = ee_s[t * 128 + cl], e1 = ee_s[t * 128 + cl + 1];
                int rr = r0 + mt * 16;
                dist_s[cl * DSTRIDE + rr]           = fmaf(-2.f, acc[mt][j][0], e0);
                dist_s[(cl + 1) * DSTRIDE + rr]     = fmaf(-2.f, acc[mt][j][1], e1);
                dist_s[cl * DSTRIDE + rr + 8]       = fmaf(-2.f, acc[mt][j][2], e0);
                dist_s[(cl + 1) * DSTRIDE + rr + 8] = fmaf(-2.f, acc[mt][j][3], e1);
            }
        __syncthreads();

        if (tid < 128) {                    // thread = row: scan 128 cols ascending
            for (int c = 0; c < 128; ++c) {
                float v = dist_s[c * DSTRIDE + tid];
                if (v < v1) v1 = v;
                if (v <= v1 + MARGIN && !ovf) {
                    if (cnt == 16) {        // compact: drop stale
                        const float thr = v1 + MARGIN;
                        int m = 0;
                        #pragma unroll
                        for (int q = 0; q < 16; ++q)
                            if (cval[q] <= thr) { cval[m] = cval[q]; cidx[m] = cidx[q]; ++m; }
                        cnt = m;
                        if (cnt == 16) ovf = true;
                    }
                    if (!ovf) { cval[cnt] = v; cidx[cnt] = (unsigned short)(t * 128 + c); ++cnt; }
                }
            }
        }
        CP_WAIT0();
        __syncthreads();
    }

    if (tid < 128) {
        if (!ovf) {                         // final compact (ascending order preserved)
            const float thr = v1 + MARGIN;
            int m = 0;
            #pragma unroll
            for (int q = 0; q < 16; ++q)
                if (q < cnt && cval[q] <= thr) { cidx[m] = cidx[q]; ++m; }
            cnt = m;
            if (cnt > 16) cnt = 16;
        }
        unsigned* gc = &g_cand[(row0 + tid) * 9];
        gc[0] = (ovf || cnt > 16) ? 255u : (unsigned)cnt;
        #pragma unroll
        for (int q = 0; q < 8; ++q) {
            unsigned lo = (2 * q     < cnt) ? (unsigned)cidx[2 * q]     : 0u;
            unsigned hi = (2 * q + 1 < cnt) ? (unsigned)cidx[2 * q + 1] : 0u;
            gc[1 + q] = lo | (hi << 16);
        }
    }
}

// ---------------- kernel 3: exact re-rank + fused output epilogue ----------------
#define XT_STRIDE 129
#define SMEM_EXACT (256 * XT_STRIDE * 4 + 16)

__global__ __launch_bounds__(128, 1)
void vq_exact(const float* __restrict__ x,
              const float* __restrict__ cb,
              float* __restrict__ out) {
    extern __shared__ char smem[];
    float* xsT = (float*)smem;                          // [256][129]
    float* warp_ls = (float*)(smem + 256 * XT_STRIDE * 4);
    const int tid = threadIdx.x;
    const long long row0 = (long long)blockIdx.x * 128;

    for (int j = 0; j < 256; ++j) {                     // coalesced load + transpose
        int g = j * 128 + tid;
        xsT[(g & 255) * XT_STRIDE + (g >> 8)] = __ldg(&x[row0 * DIM + g]);
    }
    __syncthreads();

    // exact ||x||^2 sequential ascending chain (bit-exact vs reference)
    float xx = 0.f;
    #pragma unroll 8
    for (int k = 0; k < 256; ++k) {
        float v = xsT[k * XT_STRIDE + tid];
        xx = __fadd_rn(xx, __fmul_rn(v, v));
    }

    const unsigned* gc = &g_cand[(row0 + tid) * 9];
    int cnt = (int)__ldg(&gc[0]);
    int sel = 0;
    if (cnt != 255) {
        int idxs[16];
        #pragma unroll
        for (int q = 0; q < 8; ++q) {
            unsigned w = __ldg(&gc[1 + q]);
            idxs[2 * q] = (int)(w & 0xFFFFu); idxs[2 * q + 1] = (int)(w >> 16);
        }
        float best = FLT_MAX;
        for (int c = 0; c < cnt; ++c) {
            int ki = idxs[c];
            const float* er = cb + (long long)ki * DIM;
            float a = 0.f;
            #pragma unroll 8
            for (int k = 0; k < 256; ++k)
                a = fmaf(xsT[k * XT_STRIDE + tid], __ldg(&er[k]), a);  // ascending-k exact
            float t = __fadd_rn(xx, __ldg(&g_ee[ki]));
            float d = __fadd_rn(t, __fmul_rn(-2.0f, a));
            if (d < best) { best = d; sel = ki; }        // strict < + ascending = lowest idx
        }
    } else {                                             // overflow fallback: full exact scan
        float best = FLT_MAX;
        for (int ki = 0; ki < KCODES; ++ki) {
            const float* er = cb + (long long)ki * DIM;
            float a = 0.f;
            for (int k = 0; k < 256; ++k)
                a = fmaf(xsT[k * XT_STRIDE + tid], __ldg(&er[k]), a);
            float t = __fadd_rn(xx, __ldg(&g_ee[ki]));
            float d = __fadd_rn(t, __fmul_rn(-2.0f, a));
            if (d < best) { best = d; sel = ki; }
        }
    }

    // epilogue: gather + straight-through (in place) + loss + histogram
    atomicAdd(&g_counts[sel], 1);
    const float* qr = cb + (long long)sel * DIM;
    float ls = 0.f;
    #pragma unroll 4
    for (int k = 0; k < 256; ++k) {
        float xv = xsT[k * XT_STRIDE + tid];
        float q  = __ldg(&qr[k]);
        float df = __fadd_rn(q, -xv);
        xsT[k * XT_STRIDE + tid] = __fadd_rn(xv, df);    // fl(x + fl(q-x))
        ls = fmaf(df, df, ls);
    }
    #pragma unroll
    for (int o = 16; o > 0; o >>= 1) ls += __shfl_xor_sync(0xffffffffu, ls, o);
    if ((tid & 31) == 0) warp_ls[tid >> 5] = ls;
    __syncthreads();                                     // also orders xsT for dump
    if (tid == 0)
        atomicAdd(&g_losssum, (double)(warp_ls[0] + warp_ls[1] + warp_ls[2] + warp_ls[3]));

    for (int j = 0; j < 256; ++j) {                      // coalesced transposed dump
        int g = j * 128 + tid;
        out[row0 * DIM + g] = xsT[(g & 255) * XT_STRIDE + (g >> 8)];
    }
}

// ---------------- kernel 4: loss + perplexity ----------------
__global__ void vq_finalize(float* __restrict__ out) {
    __shared__ float sh[1024];
    const int t = threadIdx.x;
    float p = (float)g_counts[t] * (1.0f / (float)NROWS);
    sh[t] = p * logf(p + 1e-10f);
    __syncthreads();
    for (int o = 512; o > 0; o >>= 1) {
        if (t < o) sh[t] += sh[t + o];
        __syncthreads();
    }
    if (t == 0) {
        double mean = g_losssum / (double)NQ;
        float  m    = (float)mean;
        out[NQ]     = __fadd_rn(m, __fmul_rn(0.25f, m));
        out[NQ + 1] = expf(-sh[0]);
    }
}

// ---------------- launch ----------------
extern "C" void kernel_launch(void* const* d_in, const int* in_sizes, int n_in,
                              void* d_out, int out_size) {
    const float* x  = (const float*)d_in[0];
    const float* cb = (const float*)d_in[1];
    float* out = (float*)d_out;

    cudaFuncSetAttribute(vq_mma,   cudaFuncAttributeMaxDynamicSharedMemorySize, SMEM_MMA);
    cudaFuncSetAttribute(vq_exact, cudaFuncAttributeMaxDynamicSharedMemorySize, SMEM_EXACT);

    vq_prep<<<256, 256>>>(cb);
    vq_mma<<<NROWS / 128, 256, SMEM_MMA>>>(x);
    vq_exact<<<NROWS / 128, 128, SMEM_EXACT>>>(x, cb, out);
    vq_finalize<<<1, 1024>>>(out);
}

// round 11
// speedup vs baseline: 2.2733x; 1.5107x over previous
#include <cuda_runtime.h>
#include <cuda_bf16.h>
#include <cfloat>
#include <cstdint>
#include <math.h>

#define NROWS   262144
#define DIM     256
#define KCODES  1024
#define NQ      67108864
#define MARGIN  8e-4f

// ---------------- scratch (no allocations) ----------------
__device__ float  g_ee[KCODES];
__device__ int    g_counts[KCODES];
__device__ double g_losssum;
__device__ __align__(1024) unsigned char g_cb_sw[8 * 65536]; // bf16 codebook, 8 N-tiles, swizzled rows
__device__ unsigned g_cand[NROWS * 9];                        // [count][8 x packed u16 idx]

// ---------------- PTX helpers (baseline sm_80/90 features only) ----------------
__device__ __forceinline__ unsigned smem_u32(const void* p) {
    unsigned a;
    asm("{ .reg .u64 t; cvta.to.shared.u64 t, %1; cvt.u32.u64 %0, t; }" : "=r"(a) : "l"(p));
    return a;
}
#define CP16(dst, src) asm volatile("cp.async.cg.shared.global [%0], [%1], 16;" :: "r"(dst), "l"(src) : "memory")
#define CP_COMMIT()    asm volatile("cp.async.commit_group;" ::: "memory")
#define CP_WAIT0()     asm volatile("cp.async.wait_group 0;" ::: "memory")
#define LDSM4(r, a) \
    asm volatile("ldmatrix.sync.aligned.m8n8.x4.shared.b16 {%0,%1,%2,%3}, [%4];" \
        : "=r"((r)[0]), "=r"((r)[1]), "=r"((r)[2]), "=r"((r)[3]) : "r"(a))

__device__ __forceinline__ void mma16816(float* d, const unsigned* a, unsigned b0, unsigned b1) {
    asm volatile("mma.sync.aligned.m16n8k16.row.col.f32.bf16.bf16.f32 "
        "{%0,%1,%2,%3}, {%4,%5,%6,%7}, {%8,%9}, {%0,%1,%2,%3};"
        : "+f"(d[0]), "+f"(d[1]), "+f"(d[2]), "+f"(d[3])
        : "r"(a[0]), "r"(a[1]), "r"(a[2]), "r"(a[3]), "r"(b0), "r"(b1));
}

// Row layout: 512B per row (256 bf16), 32 chunks of 16B, chunk XOR-swizzled by row&7.
__device__ __forceinline__ unsigned sw_off(int row, int k8) {   // k8 = element idx, mult of 8
    return (unsigned)row * 512u + (unsigned)(((k8 >> 3) ^ (row & 7)) << 4);
}

// ---------------- kernel 1: exact ee chains + swizzled bf16 codebook + zero scratch ----------------
__global__ void vq_prep(const float* __restrict__ cb) {
    int gt = blockIdx.x * blockDim.x + threadIdx.x;
    if (gt < KCODES) {
        const float4* p = (const float4*)(cb + (long long)gt * DIM);
        float s = 0.f;
        #pragma unroll 8
        for (int i = 0; i < 64; ++i) {
            float4 v = __ldg(&p[i]);
            s = __fadd_rn(s, __fmul_rn(v.x, v.x));
            s = __fadd_rn(s, __fmul_rn(v.y, v.y));
            s = __fadd_rn(s, __fmul_rn(v.z, v.z));
            s = __fadd_rn(s, __fmul_rn(v.w, v.w));
        }
        g_ee[gt] = s;
        g_counts[gt] = 0;
    }
    if (gt == 0) g_losssum = 0.0;
    for (int i = gt * 8; i < KCODES * DIM; i += gridDim.x * blockDim.x * 8) {
        int code = i >> 8, k8 = i & 255;
        float4 f0 = __ldg((const float4*)(cb + i));
        float4 f1 = __ldg((const float4*)(cb + i) + 1);
        __nv_bfloat162 h0 = __floats2bfloat162_rn(f0.x, f0.y);
        __nv_bfloat162 h1 = __floats2bfloat162_rn(f0.z, f0.w);
        __nv_bfloat162 h2 = __floats2bfloat162_rn(f1.x, f1.y);
        __nv_bfloat162 h3 = __floats2bfloat162_rn(f1.z, f1.w);
        uint4 w = make_uint4(*(unsigned*)&h0, *(unsigned*)&h1, *(unsigned*)&h2, *(unsigned*)&h3);
        *(uint4*)(g_cb_sw + (code >> 7) * 65536 + sw_off(code & 127, k8)) = w;
    }
}

// ---------------- kernel 2: HMMA screening GEMM, in-register epilogue ----------------
#define EE_OFF    0
#define A_OFF     4096
#define B_OFF     69632            // two 64KB buffers
#define CNT_OFF   200704           // u32[128]
#define CVAL_OFF  201216           // f32[128][24]
#define CIDX_OFF  213504           // u16[128][24]
#define HMIN_OFF  219648           // f32[128][2]
#define SMEM_MMA  220672

__global__ __launch_bounds__(256, 1)
void vq_mma(const float* __restrict__ x) {
    extern __shared__ char smem[];
    const unsigned sb = smem_u32(smem);
    float* ee_s            = (float*)(smem + EE_OFF);
    unsigned* cnt_s        = (unsigned*)(smem + CNT_OFF);
    float* cval_s          = (float*)(smem + CVAL_OFF);
    unsigned short* cidx_s = (unsigned short*)(smem + CIDX_OFF);
    float* hmin_s          = (float*)(smem + HMIN_OFF);
    const int tid = threadIdx.x, wid = tid >> 5, lane = tid & 31;
    const long long row0 = (long long)blockIdx.x * 128;

    if (tid < 128) cnt_s[tid] = 0;
    #pragma unroll
    for (int i = 0; i < 4; ++i) ee_s[tid + i * 256] = g_ee[tid + i * 256];

    // prefetch B tile 0 into buffer 0
    #pragma unroll
    for (int j = 0; j < 16; ++j) {
        unsigned off = (unsigned)(tid + j * 256) * 16u;
        CP16(sb + B_OFF + off, (const char*)g_cb_sw + off);
    }
    CP_COMMIT();

    // build A: 128 rows x 256 k -> bf16 swizzled (coalesced ldg, conflict-free sts)
    #pragma unroll
    for (int i = 0; i < 16; ++i) {
        int c = tid + i * 256;                  // 0..4095
        int row = c >> 5, kc = (c & 31) * 8;
        const float4* gp = (const float4*)(x + (row0 + row) * DIM + kc);
        float4 f0 = __ldg(gp), f1 = __ldg(gp + 1);
        __nv_bfloat162 h0 = __floats2bfloat162_rn(f0.x, f0.y);
        __nv_bfloat162 h1 = __floats2bfloat162_rn(f0.z, f0.w);
        __nv_bfloat162 h2 = __floats2bfloat162_rn(f1.x, f1.y);
        __nv_bfloat162 h3 = __floats2bfloat162_rn(f1.z, f1.w);
        uint4 w = make_uint4(*(unsigned*)&h0, *(unsigned*)&h1, *(unsigned*)&h2, *(unsigned*)&h3);
        *(uint4*)(smem + A_OFF + sw_off(row, kc)) = w;
    }

    // warp tiling: 4 (rows) x 2 (cols); warp = 32 rows x 64 cols  (identical to R10)
    const int mrow0 = (wid >> 1) * 32;
    const int ncol0 = (wid & 1) * 64;
    const int arow  = lane & 15;
    const int akc   = lane >> 4;
    const int bn    = ((lane >> 4) << 3) + (lane & 7);
    const int bkc   = (lane >> 3) & 1;

    float rowmin[2][2] = {{FLT_MAX, FLT_MAX}, {FLT_MAX, FLT_MAX}};

    for (int t = 0; t < 8; ++t) {
        CP_WAIT0();                 // B(t) arrived (only outstanding group)
        __syncthreads();            // all warps done with buffer (t&1) from tile t-2; A visible at t=0
        const unsigned bbuf = sb + B_OFF + (unsigned)(t & 1) * 65536u;
        if (t < 7) {                // prefetch B(t+1) under MMA(t)
            const unsigned nbuf = sb + B_OFF + (unsigned)((t + 1) & 1) * 65536u;
            #pragma unroll
            for (int j = 0; j < 16; ++j) {
                unsigned off = (unsigned)(tid + j * 256) * 16u;
                CP16(nbuf + off, (const char*)g_cb_sw + (t + 1) * 65536 + off);
            }
            CP_COMMIT();
        }

        float acc[2][8][4];
        #pragma unroll
        for (int mt = 0; mt < 2; ++mt)
            #pragma unroll
            for (int j = 0; j < 8; ++j)
                #pragma unroll
                for (int q = 0; q < 4; ++q) acc[mt][j][q] = 0.f;

        #pragma unroll
        for (int ks = 0; ks < 16; ++ks) {
            unsigned a[2][4], b[4][4];
            #pragma unroll
            for (int mt = 0; mt < 2; ++mt) {
                int r = mrow0 + mt * 16 + arow;
                LDSM4(a[mt], sb + A_OFF + (unsigned)r * 512u + (unsigned)(((ks * 2 + akc) ^ (r & 7)) << 4));
            }
            #pragma unroll
            for (int nt = 0; nt < 4; ++nt) {
                int n = ncol0 + nt * 16 + bn;
                LDSM4(b[nt], bbuf + (unsigned)n * 512u + (unsigned)(((ks * 2 + bkc) ^ (n & 7)) << 4));
            }
            #pragma unroll
            for (int mt = 0; mt < 2; ++mt)
                #pragma unroll
                for (int j = 0; j < 8; ++j)
                    mma16816(acc[mt][j], a[mt], b[j >> 1][(j & 1) * 2], b[j >> 1][(j & 1) * 2 + 1]);
        }

        // ---- in-register epilogue: distances, quad-reduced row min, candidate push ----
        #pragma unroll
        for (int mt = 0; mt < 2; ++mt)
            #pragma unroll
            for (int j = 0; j < 8; ++j) {
                int cl = ncol0 + j * 8 + (lane & 3) * 2;
                float e0 = ee_s[t * 128 + cl], e1 = ee_s[t * 128 + cl + 1];
                acc[mt][j][0] = fmaf(-2.f, acc[mt][j][0], e0);
                acc[mt][j][1] = fmaf(-2.f, acc[mt][j][1], e1);
                acc[mt][j][2] = fmaf(-2.f, acc[mt][j][2], e0);
                acc[mt][j][3] = fmaf(-2.f, acc[mt][j][3], e1);
            }
        #pragma unroll
        for (int mt = 0; mt < 2; ++mt)
            #pragma unroll
            for (int h = 0; h < 2; ++h) {
                float m = FLT_MAX;
                #pragma unroll
                for (int j = 0; j < 8; ++j)
                    m = fminf(m, fminf(acc[mt][j][h * 2], acc[mt][j][h * 2 + 1]));
                m = fminf(m, __shfl_xor_sync(0xffffffffu, m, 1));   // quad owns row's 64 cols
                m = fminf(m, __shfl_xor_sync(0xffffffffu, m, 2));
                rowmin[mt][h] = fminf(rowmin[mt][h], m);
                const float thr = rowmin[mt][h] + MARGIN;
                const int row = mrow0 + mt * 16 + h * 8 + (lane >> 2);
                #pragma unroll
                for (int j = 0; j < 8; ++j)
                    #pragma unroll
                    for (int q = 0; q < 2; ++q) {
                        float v = acc[mt][j][h * 2 + q];
                        if (v <= thr) {
                            unsigned s = atomicAdd(&cnt_s[row], 1u);
                            if (s < 24) {
                                cval_s[row * 24 + s] = v;
                                cidx_s[row * 24 + s] =
                                    (unsigned short)(t * 128 + ncol0 + j * 8 + (lane & 3) * 2 + q);
                            }
                        }
                    }
            }
    }

    // combine col-half minima, final filter, write candidate lists
    if ((lane & 3) == 0) {
        #pragma unroll
        for (int mt = 0; mt < 2; ++mt)
            #pragma unroll
            for (int h = 0; h < 2; ++h) {
                int row = mrow0 + mt * 16 + h * 8 + (lane >> 2);
                hmin_s[row * 2 + (wid & 1)] = rowmin[mt][h];
            }
    }
    __syncthreads();
    if (tid < 128) {
        float fmin = fminf(hmin_s[tid * 2], hmin_s[tid * 2 + 1]);
        float thr  = fmin + MARGIN;
        unsigned n = cnt_s[tid];
        unsigned short keep[16]; int m = 0; bool ovf = (n > 24);
        if (!ovf) {
            for (unsigned s = 0; s < n; ++s) {
                if (cval_s[tid * 24 + s] <= thr) {
                    if (m < 16) keep[m++] = cidx_s[tid * 24 + s];
                    else { ovf = true; break; }
                }
            }
        }
        unsigned* gc = &g_cand[(row0 + tid) * 9];
        gc[0] = ovf ? 255u : (unsigned)m;
        #pragma unroll
        for (int q = 0; q < 8; ++q) {
            unsigned lo = (2 * q     < m) ? (unsigned)keep[2 * q]     : 0u;
            unsigned hi = (2 * q + 1 < m) ? (unsigned)keep[2 * q + 1] : 0u;
            gc[1 + q] = lo | (hi << 16);
        }
    }
}

// ---------------- kernel 3: exact re-rank + fused output epilogue ----------------
#define XT_STRIDE 129
#define SMEM_EXACT (256 * XT_STRIDE * 4 + 16)

__global__ __launch_bounds__(128, 1)
void vq_exact(const float* __restrict__ x,
              const float* __restrict__ cb,
              float* __restrict__ out) {
    extern __shared__ char smem[];
    float* xsT = (float*)smem;                          // [256][129]
    float* warp_ls = (float*)(smem + 256 * XT_STRIDE * 4);
    const int tid = threadIdx.x;
    const long long row0 = (long long)blockIdx.x * 128;

    for (int j = 0; j < 256; ++j) {                     // coalesced load + transpose
        int g = j * 128 + tid;
        xsT[(g & 255) * XT_STRIDE + (g >> 8)] = __ldg(&x[row0 * DIM + g]);
    }
    __syncthreads();

    // exact ||x||^2 sequential ascending chain (bit-exact vs reference)
    float xx = 0.f;
    #pragma unroll 8
    for (int k = 0; k < 256; ++k) {
        float v = xsT[k * XT_STRIDE + tid];
        xx = __fadd_rn(xx, __fmul_rn(v, v));
    }

    const unsigned* gc = &g_cand[(row0 + tid) * 9];
    int cnt = (int)__ldg(&gc[0]);
    int sel = 0;
    if (cnt != 255) {
        int idxs[16];
        #pragma unroll
        for (int q = 0; q < 8; ++q) {
            unsigned w = __ldg(&gc[1 + q]);
            idxs[2 * q] = (int)(w & 0xFFFFu); idxs[2 * q + 1] = (int)(w >> 16);
        }
        float best = FLT_MAX; sel = KCODES;
        for (int c = 0; c < cnt; ++c) {
            int ki = idxs[c];
            const float* er = cb + (long long)ki * DIM;
            float a = 0.f;
            #pragma unroll 8
            for (int k = 0; k < 256; ++k)
                a = fmaf(xsT[k * XT_STRIDE + tid], __ldg(&er[k]), a);  // ascending-k exact
            float t = __fadd_rn(xx, __ldg(&g_ee[ki]));
            float d = __fadd_rn(t, __fmul_rn(-2.0f, a));
            if (d < best || (d == best && ki < sel)) { best = d; sel = ki; }  // lowest-idx tie
        }
    } else {                                             // overflow fallback: full exact scan
        float best = FLT_MAX;
        for (int ki = 0; ki < KCODES; ++ki) {
            const float* er = cb + (long long)ki * DIM;
            float a = 0.f;
            for (int k = 0; k < 256; ++k)
                a = fmaf(xsT[k * XT_STRIDE + tid], __ldg(&er[k]), a);
            float t = __fadd_rn(xx, __ldg(&g_ee[ki]));
            float d = __fadd_rn(t, __fmul_rn(-2.0f, a));
            if (d < best) { best = d; sel = ki; }
        }
    }

    // epilogue: gather + straight-through (in place) + loss + histogram
    atomicAdd(&g_counts[sel], 1);
    const float* qr = cb + (long long)sel * DIM;
    float ls = 0.f;
    #pragma unroll 4
    for (int k = 0; k < 256; ++k) {
        float xv = xsT[k * XT_STRIDE + tid];
        float q  = __ldg(&qr[k]);
        float df = __fadd_rn(q, -xv);
        xsT[k * XT_STRIDE + tid] = __fadd_rn(xv, df);    // fl(x + fl(q-x))
        ls = fmaf(df, df, ls);
    }
    #pragma unroll
    for (int o = 16; o > 0; o >>= 1) ls += __shfl_xor_sync(0xffffffffu, ls, o);
    if ((tid & 31) == 0) warp_ls[tid >> 5] = ls;
    __syncthreads();                                     // also orders xsT for dump
    if (tid == 0)
        atomicAdd(&g_losssum, (double)(warp_ls[0] + warp_ls[1] + warp_ls[2] + warp_ls[3]));

    for (int j = 0; j < 256; ++j) {                      // coalesced transposed dump
        int g = j * 128 + tid;
        out[row0 * DIM + g] = xsT[(g & 255) * XT_STRIDE + (g >> 8)];
    }
}

// ---------------- kernel 4: loss + perplexity ----------------
__global__ void vq_finalize(float* __restrict__ out) {
    __shared__ float sh[1024];
    const int t = threadIdx.x;
    float p = (float)g_counts[t] * (1.0f / (float)NROWS);
    sh[t] = p * logf(p + 1e-10f);
    __syncthreads();
    for (int o = 512; o > 0; o >>= 1) {
        if (t < o) sh[t] += sh[t + o];
        __syncthreads();
    }
    if (t == 0) {
        double mean = g_losssum / (double)NQ;
        float  m    = (float)mean;
        out[NQ]     = __fadd_rn(m, __fmul_rn(0.25f, m));
        out[NQ + 1] = expf(-sh[0]);
    }
}

// ---------------- launch ----------------
extern "C" void kernel_launch(void* const* d_in, const int* in_sizes, int n_in,
                              void* d_out, int out_size) {
    const float* x  = (const float*)d_in[0];
    const float* cb = (const float*)d_in[1];
    float* out = (float*)d_out;

    cudaFuncSetAttribute(vq_mma,   cudaFuncAttributeMaxDynamicSharedMemorySize, SMEM_MMA);
    cudaFuncSetAttribute(vq_exact, cudaFuncAttributeMaxDynamicSharedMemorySize, SMEM_EXACT);

    vq_prep<<<256, 256>>>(cb);
    vq_mma<<<NROWS / 128, 256, SMEM_MMA>>>(x);
    vq_exact<<<NROWS / 128, 128, SMEM_EXACT>>>(x, cb, out);
    vq_finalize<<<1, 1024>>>(out);
}